// round 1
// baseline (speedup 1.0000x reference)
#include <cuda_runtime.h>
#include <cstddef>

#define B 32
#define T 2048
#define E 128
#define NS 16
#define RPC (T / NS)   // 128 rows per chunk
#define INV_T (1.0f / 2048.0f)

// ---------------- scratch (device globals; no allocation allowed) ----------
__device__ float g_s_part[2][B][NS][E];   // partial column sums of x1 / x2
__device__ float g_c_part[2][B][NS][E];   // partial c1 / c2 (unscaled)
__device__ float g_d[2][B][T];            // d1 = x1.W1, d2 = x2.W2
__device__ float g_et[2][B][T];           // logits -> overwritten with softmax weights
__device__ float g_o_part[2][B][NS][E];   // partial weighted sums

static __device__ __forceinline__ float dot4(float4 a, float4 b) {
    return fmaf(a.x, b.x, fmaf(a.y, b.y, fmaf(a.z, b.z, a.w * b.w)));
}

// ===========================================================================
// K1: column sums s1[b][e] = sum_t x1[b][t][e], same for x2 (partials per chunk)
// grid (NS, B), block 256 = 8 row-groups x 32 float4 lanes
// ===========================================================================
__global__ void __launch_bounds__(256) k1_sums(
    const float* __restrict__ x1, const float* __restrict__ x2)
{
    int chunk = blockIdx.x, b = blockIdx.y;
    int lane = threadIdx.x & 31, grp = threadIdx.x >> 5;
    int t0 = chunk * RPC;
    const float4* p1 = (const float4*)(x1 + ((size_t)b * T + t0) * E) + lane;
    const float4* p2 = (const float4*)(x2 + ((size_t)b * T + t0) * E) + lane;

    float4 a1 = {0,0,0,0}, a2 = {0,0,0,0};
    #pragma unroll 4
    for (int r = grp; r < RPC; r += 8) {
        float4 v1 = p1[r * (E/4)];
        float4 v2 = p2[r * (E/4)];
        a1.x += v1.x; a1.y += v1.y; a1.z += v1.z; a1.w += v1.w;
        a2.x += v2.x; a2.y += v2.y; a2.z += v2.z; a2.w += v2.w;
    }
    __shared__ float4 sh1[8][32], sh2[8][32];
    sh1[grp][lane] = a1;
    sh2[grp][lane] = a2;
    __syncthreads();
    if (threadIdx.x < 32) {
        float4 s = sh1[0][lane];
        #pragma unroll
        for (int g = 1; g < 8; g++) {
            float4 v = sh1[g][lane];
            s.x += v.x; s.y += v.y; s.z += v.z; s.w += v.w;
        }
        ((float4*)&g_s_part[0][b][chunk][0])[lane] = s;
    } else if (threadIdx.x < 64) {
        float4 s = sh2[0][lane];
        #pragma unroll
        for (int g = 1; g < 8; g++) {
            float4 v = sh2[g][lane];
            s.x += v.x; s.y += v.y; s.z += v.z; s.w += v.w;
        }
        ((float4*)&g_s_part[1][b][chunk][0])[lane] = s;
    }
}

// ===========================================================================
// K3: per-row scalars a1 = x1[t].s2, a2 = x2[t].s1, d1 = x1[t].W1, d2 = x2[t].W2
//     accumulate c1 += a1*x2[t], c2 += a2*x1[t]  (partials per chunk)
// grid (NS, B), block 256 = 8 warps, 16 rows per warp
// ===========================================================================
__global__ void __launch_bounds__(256) k3_cd(
    const float* __restrict__ x1, const float* __restrict__ x2,
    const float* __restrict__ W1, const float* __restrict__ W2)
{
    int chunk = blockIdx.x, b = blockIdx.y;
    int lane = threadIdx.x & 31, w = threadIdx.x >> 5;

    __shared__ float s_sh[2][E];
    __shared__ float w_sh[2][E];
    if (threadIdx.x < 128) {
        int e = threadIdx.x;
        float acc = 0.f;
        #pragma unroll
        for (int ch = 0; ch < NS; ch++) acc += g_s_part[0][b][ch][e];
        s_sh[0][e] = acc;
        w_sh[0][e] = W1[e];
    } else {
        int e = threadIdx.x - 128;
        float acc = 0.f;
        #pragma unroll
        for (int ch = 0; ch < NS; ch++) acc += g_s_part[1][b][ch][e];
        s_sh[1][e] = acc;
        w_sh[1][e] = W2[e];
    }
    __syncthreads();

    float4 s1l = ((const float4*)s_sh[0])[lane];
    float4 s2l = ((const float4*)s_sh[1])[lane];
    float4 w1l = ((const float4*)w_sh[0])[lane];
    float4 w2l = ((const float4*)w_sh[1])[lane];

    int t0 = chunk * RPC + w * 16;
    const float4* p1 = (const float4*)(x1 + ((size_t)b * T + t0) * E) + lane;
    const float4* p2 = (const float4*)(x2 + ((size_t)b * T + t0) * E) + lane;

    float4 c1a = {0,0,0,0}, c2a = {0,0,0,0};
    for (int rr = 0; rr < 16; rr++) {
        float4 v1 = p1[rr * (E/4)];
        float4 v2 = p2[rr * (E/4)];
        float a1 = dot4(v1, s2l);   // x1 . s2
        float a2 = dot4(v2, s1l);   // x2 . s1
        float d1 = dot4(v1, w1l);   // x1 . W1
        float d2 = dot4(v2, w2l);   // x2 . W2
        #pragma unroll
        for (int off = 16; off; off >>= 1) {
            a1 += __shfl_xor_sync(0xffffffffu, a1, off);
            a2 += __shfl_xor_sync(0xffffffffu, a2, off);
            d1 += __shfl_xor_sync(0xffffffffu, d1, off);
            d2 += __shfl_xor_sync(0xffffffffu, d2, off);
        }
        c1a.x = fmaf(a1, v2.x, c1a.x); c1a.y = fmaf(a1, v2.y, c1a.y);
        c1a.z = fmaf(a1, v2.z, c1a.z); c1a.w = fmaf(a1, v2.w, c1a.w);
        c2a.x = fmaf(a2, v1.x, c2a.x); c2a.y = fmaf(a2, v1.y, c2a.y);
        c2a.z = fmaf(a2, v1.z, c2a.z); c2a.w = fmaf(a2, v1.w, c2a.w);
        if (lane == 0) {
            g_d[0][b][t0 + rr] = d1;
            g_d[1][b][t0 + rr] = d2;
        }
    }

    __shared__ float4 shc[2][8][32];
    shc[0][w][lane] = c1a;
    shc[1][w][lane] = c2a;
    __syncthreads();
    if (threadIdx.x < 32) {
        float4 s = shc[0][0][lane];
        #pragma unroll
        for (int g = 1; g < 8; g++) {
            float4 v = shc[0][g][lane];
            s.x += v.x; s.y += v.y; s.z += v.z; s.w += v.w;
        }
        ((float4*)&g_c_part[0][b][chunk][0])[lane] = s;
    } else if (threadIdx.x < 64) {
        float4 s = shc[1][0][lane];
        #pragma unroll
        for (int g = 1; g < 8; g++) {
            float4 v = shc[1][g][lane];
            s.x += v.x; s.y += v.y; s.z += v.z; s.w += v.w;
        }
        ((float4*)&g_c_part[1][b][chunk][0])[lane] = s;
    }
}

// ===========================================================================
// K5: et[ti][b][t] = sum_e c[ti][b][e] * U[e][t] + d[ti][b][t] + bias[t]
// grid (T/128, 4, 2), block 256: 8 batches per block, thread -> float4 of t
// ===========================================================================
__global__ void __launch_bounds__(256) k5_et(
    const float* __restrict__ U1, const float* __restrict__ U2,
    const float* __restrict__ b1, const float* __restrict__ b2)
{
    int tb = blockIdx.x;          // 0..15
    int bg = blockIdx.y;          // 0..3
    int ti = blockIdx.z;          // 0..1
    const float* U = ti ? U2 : U1;
    const float* bias = ti ? b2 : b1;
    int b0 = bg * 8, t0 = tb * 128;

    __shared__ float csh[8][E];
    for (int idx = threadIdx.x; idx < 8 * E; idx += 256) {
        int bi = idx >> 7, e = idx & 127;
        float acc = 0.f;
        #pragma unroll
        for (int ch = 0; ch < NS; ch++) acc += g_c_part[ti][b0 + bi][ch][e];
        csh[bi][e] = acc * INV_T;
    }
    __syncthreads();

    int bi = threadIdx.x >> 5, lane = threadIdx.x & 31;
    const float4* U4 = (const float4*)(U + t0) + lane;
    float4 acc = {0,0,0,0};
    #pragma unroll 8
    for (int e = 0; e < E; e++) {
        float c = csh[bi][e];
        float4 u = U4[e * (T/4)];
        acc.x = fmaf(c, u.x, acc.x);
        acc.y = fmaf(c, u.y, acc.y);
        acc.z = fmaf(c, u.z, acc.z);
        acc.w = fmaf(c, u.w, acc.w);
    }
    int t = t0 + lane * 4;
    float4 dd = *(const float4*)&g_d[ti][b0 + bi][t];
    float4 bb = *(const float4*)(bias + t);
    acc.x += dd.x + bb.x;
    acc.y += dd.y + bb.y;
    acc.z += dd.z + bb.z;
    acc.w += dd.w + bb.w;
    *(float4*)&g_et[ti][b0 + bi][t] = acc;
}

// ===========================================================================
// K6: softmax over T per (ti, b); overwrite g_et with normalized weights
// grid (B, 2), block 256, 8 elements per thread
// ===========================================================================
__global__ void __launch_bounds__(256) k6_softmax()
{
    int b = blockIdx.x, ti = blockIdx.y;
    float* et = g_et[ti][b];
    int tid = threadIdx.x;

    float v[8];
    float m = -3.4e38f;
    #pragma unroll
    for (int k = 0; k < 8; k++) {
        v[k] = et[tid + k * 256];
        m = fmaxf(m, v[k]);
    }
    __shared__ float red[256];
    red[tid] = m;
    __syncthreads();
    #pragma unroll
    for (int s = 128; s; s >>= 1) {
        if (tid < s) red[tid] = fmaxf(red[tid], red[tid + s]);
        __syncthreads();
    }
    m = red[0];
    __syncthreads();

    float z = 0.f;
    #pragma unroll
    for (int k = 0; k < 8; k++) {
        v[k] = expf(v[k] - m);
        z += v[k];
    }
    red[tid] = z;
    __syncthreads();
    #pragma unroll
    for (int s = 128; s; s >>= 1) {
        if (tid < s) red[tid] = red[tid] + red[tid + s];
        __syncthreads();
    }
    float iz = 1.0f / red[0];
    #pragma unroll
    for (int k = 0; k < 8; k++) et[tid + k * 256] = v[k] * iz;
}

// ===========================================================================
// K7: o[ti][b][e] = sum_t w[ti][b][t] * x[ti][b][t][e]  (partials per chunk)
// grid (NS, B), block 256 like K1
// ===========================================================================
__global__ void __launch_bounds__(256) k7_o(
    const float* __restrict__ x1, const float* __restrict__ x2)
{
    int chunk = blockIdx.x, b = blockIdx.y;
    int lane = threadIdx.x & 31, grp = threadIdx.x >> 5;
    int t0 = chunk * RPC;
    const float4* p1 = (const float4*)(x1 + ((size_t)b * T + t0) * E) + lane;
    const float4* p2 = (const float4*)(x2 + ((size_t)b * T + t0) * E) + lane;

    float4 a1 = {0,0,0,0}, a2 = {0,0,0,0};
    #pragma unroll 4
    for (int r = grp; r < RPC; r += 8) {
        float w1 = g_et[0][b][t0 + r];
        float w2 = g_et[1][b][t0 + r];
        float4 v1 = p1[r * (E/4)];
        float4 v2 = p2[r * (E/4)];
        a1.x = fmaf(w1, v1.x, a1.x); a1.y = fmaf(w1, v1.y, a1.y);
        a1.z = fmaf(w1, v1.z, a1.z); a1.w = fmaf(w1, v1.w, a1.w);
        a2.x = fmaf(w2, v2.x, a2.x); a2.y = fmaf(w2, v2.y, a2.y);
        a2.z = fmaf(w2, v2.z, a2.z); a2.w = fmaf(w2, v2.w, a2.w);
    }
    __shared__ float4 sh1[8][32], sh2[8][32];
    sh1[grp][lane] = a1;
    sh2[grp][lane] = a2;
    __syncthreads();
    if (threadIdx.x < 32) {
        float4 s = sh1[0][lane];
        #pragma unroll
        for (int g = 1; g < 8; g++) {
            float4 v = sh1[g][lane];
            s.x += v.x; s.y += v.y; s.z += v.z; s.w += v.w;
        }
        ((float4*)&g_o_part[0][b][chunk][0])[lane] = s;
    } else if (threadIdx.x < 64) {
        float4 s = sh2[0][lane];
        #pragma unroll
        for (int g = 1; g < 8; g++) {
            float4 v = sh2[g][lane];
            s.x += v.x; s.y += v.y; s.z += v.z; s.w += v.w;
        }
        ((float4*)&g_o_part[1][b][chunk][0])[lane] = s;
    }
}

// ===========================================================================
// K8: final reduce -> out[b][0:128] = o1, out[b][128:256] = o2
// grid (B), block 256
// ===========================================================================
__global__ void __launch_bounds__(256) k8_out(float* __restrict__ out)
{
    int b = blockIdx.x;
    int tid = threadIdx.x;
    if (tid < 128) {
        int e = tid;
        float acc = 0.f;
        #pragma unroll
        for (int ch = 0; ch < NS; ch++) acc += g_o_part[0][b][ch][e];
        out[b * 256 + e] = acc;
    } else {
        int e = tid - 128;
        float acc = 0.f;
        #pragma unroll
        for (int ch = 0; ch < NS; ch++) acc += g_o_part[1][b][ch][e];
        out[b * 256 + 128 + e] = acc;
    }
}

// ===========================================================================
extern "C" void kernel_launch(void* const* d_in, const int* in_sizes, int n_in,
                              void* d_out, int out_size)
{
    const float* x1 = (const float*)d_in[0];
    const float* x2 = (const float*)d_in[1];
    const float* W1 = (const float*)d_in[2];
    const float* b1 = (const float*)d_in[3];
    const float* U1 = (const float*)d_in[4];
    const float* W2 = (const float*)d_in[5];
    const float* b2 = (const float*)d_in[6];
    const float* U2 = (const float*)d_in[7];
    float* out = (float*)d_out;

    k1_sums<<<dim3(NS, B), 256>>>(x1, x2);
    k3_cd<<<dim3(NS, B), 256>>>(x1, x2, W1, W2);
    k5_et<<<dim3(T / 128, 4, 2), 256>>>(U1, U2, b1, b2);
    k6_softmax<<<dim3(B, 2), 256>>>();
    k7_o<<<dim3(NS, B), 256>>>(x1, x2);
    k8_out<<<B, 256>>>(out);
}

// round 3
// speedup vs baseline: 1.0122x; 1.0122x over previous
#include <cuda_runtime.h>
#include <cstddef>

#define B 32
#define T 2048
#define E 128
#define NS 16
#define RPC (T / NS)   // 128 rows per chunk (== k5 t-tile size)
#define INV_T (1.0f / 2048.0f)

// ---------------- scratch (device globals; no allocation allowed) ----------
__device__ float  g_s_part[2][B][NS][E];   // partial column sums of x1 / x2
__device__ float  g_c_part[2][B][NS][E];   // partial c1 / c2 (unscaled)
__device__ float  g_d[2][B][T];            // d1 = x1.W1, d2 = x2.W2
__device__ float  g_et[2][B][T];           // raw logits
__device__ float2 g_stats[2][B][NS];       // per-tile (max, sumexp(local max))
__device__ float  g_o_part[2][B][NS][E];   // partial weighted sums
__device__ unsigned int g_ticket[B];       // zero-init; atomicInc wraps -> 0 each run

static __device__ __forceinline__ float dot4(float4 a, float4 b) {
    return fmaf(a.x, b.x, fmaf(a.y, b.y, fmaf(a.z, b.z, a.w * b.w)));
}

// ===========================================================================
// K1: column-sum partials s1/s2 AND per-row dots d1 = x1.W1, d2 = x2.W2
// grid (NS, B), block 256 = 8 warps; warp w owns 16 contiguous rows
// ===========================================================================
__global__ void __launch_bounds__(256) k1_sd(
    const float* __restrict__ x1, const float* __restrict__ x2,
    const float* __restrict__ W1, const float* __restrict__ W2)
{
    int chunk = blockIdx.x, b = blockIdx.y;
    int lane = threadIdx.x & 31, w = threadIdx.x >> 5;

    float4 w1l = ((const float4*)W1)[lane];
    float4 w2l = ((const float4*)W2)[lane];

    int t0 = chunk * RPC + w * 16;
    const float4* p1 = (const float4*)(x1 + ((size_t)b * T + t0) * E) + lane;
    const float4* p2 = (const float4*)(x2 + ((size_t)b * T + t0) * E) + lane;

    float4 s1a = {0,0,0,0}, s2a = {0,0,0,0};
    #pragma unroll 4
    for (int rr = 0; rr < 16; rr++) {
        float4 v1 = p1[rr * (E/4)];
        float4 v2 = p2[rr * (E/4)];
        s1a.x += v1.x; s1a.y += v1.y; s1a.z += v1.z; s1a.w += v1.w;
        s2a.x += v2.x; s2a.y += v2.y; s2a.z += v2.z; s2a.w += v2.w;
        float d1 = dot4(v1, w1l);
        float d2 = dot4(v2, w2l);
        #pragma unroll
        for (int off = 16; off; off >>= 1) {
            d1 += __shfl_xor_sync(0xffffffffu, d1, off);
            d2 += __shfl_xor_sync(0xffffffffu, d2, off);
        }
        if (lane == 0) {
            g_d[0][b][t0 + rr] = d1;
            g_d[1][b][t0 + rr] = d2;
        }
    }

    __shared__ float4 sh1[8][32], sh2[8][32];
    sh1[w][lane] = s1a;
    sh2[w][lane] = s2a;
    __syncthreads();
    if (threadIdx.x < 32) {
        float4 s = sh1[0][lane];
        #pragma unroll
        for (int g = 1; g < 8; g++) {
            float4 v = sh1[g][lane];
            s.x += v.x; s.y += v.y; s.z += v.z; s.w += v.w;
        }
        ((float4*)&g_s_part[0][b][chunk][0])[lane] = s;
    } else if (threadIdx.x < 64) {
        float4 s = sh2[0][lane];
        #pragma unroll
        for (int g = 1; g < 8; g++) {
            float4 v = sh2[g][lane];
            s.x += v.x; s.y += v.y; s.z += v.z; s.w += v.w;
        }
        ((float4*)&g_s_part[1][b][chunk][0])[lane] = s;
    }
}

// ===========================================================================
// K3: a1 = x1[t].s2, a2 = x2[t].s1; accumulate c1 += a1*x2[t], c2 += a2*x1[t]
// grid (NS, B), block 256 = 8 warps, 16 rows per warp
// ===========================================================================
__global__ void __launch_bounds__(256) k3_c(
    const float* __restrict__ x1, const float* __restrict__ x2)
{
    int chunk = blockIdx.x, b = blockIdx.y;
    int lane = threadIdx.x & 31, w = threadIdx.x >> 5;

    __shared__ float s_sh[2][E];
    if (threadIdx.x < 128) {
        int e = threadIdx.x;
        float acc = 0.f;
        #pragma unroll
        for (int ch = 0; ch < NS; ch++) acc += g_s_part[0][b][ch][e];
        s_sh[0][e] = acc;
    } else {
        int e = threadIdx.x - 128;
        float acc = 0.f;
        #pragma unroll
        for (int ch = 0; ch < NS; ch++) acc += g_s_part[1][b][ch][e];
        s_sh[1][e] = acc;
    }
    __syncthreads();

    float4 s1l = ((const float4*)s_sh[0])[lane];
    float4 s2l = ((const float4*)s_sh[1])[lane];

    int t0 = chunk * RPC + w * 16;
    const float4* p1 = (const float4*)(x1 + ((size_t)b * T + t0) * E) + lane;
    const float4* p2 = (const float4*)(x2 + ((size_t)b * T + t0) * E) + lane;

    float4 c1a = {0,0,0,0}, c2a = {0,0,0,0};
    #pragma unroll 2
    for (int rr = 0; rr < 16; rr++) {
        float4 v1 = p1[rr * (E/4)];
        float4 v2 = p2[rr * (E/4)];
        float a1 = dot4(v1, s2l);   // x1 . s2
        float a2 = dot4(v2, s1l);   // x2 . s1
        #pragma unroll
        for (int off = 16; off; off >>= 1) {
            a1 += __shfl_xor_sync(0xffffffffu, a1, off);
            a2 += __shfl_xor_sync(0xffffffffu, a2, off);
        }
        c1a.x = fmaf(a1, v2.x, c1a.x); c1a.y = fmaf(a1, v2.y, c1a.y);
        c1a.z = fmaf(a1, v2.z, c1a.z); c1a.w = fmaf(a1, v2.w, c1a.w);
        c2a.x = fmaf(a2, v1.x, c2a.x); c2a.y = fmaf(a2, v1.y, c2a.y);
        c2a.z = fmaf(a2, v1.z, c2a.z); c2a.w = fmaf(a2, v1.w, c2a.w);
    }

    __shared__ float4 shc[2][8][32];
    shc[0][w][lane] = c1a;
    shc[1][w][lane] = c2a;
    __syncthreads();
    if (threadIdx.x < 32) {
        float4 s = shc[0][0][lane];
        #pragma unroll
        for (int g = 1; g < 8; g++) {
            float4 v = shc[0][g][lane];
            s.x += v.x; s.y += v.y; s.z += v.z; s.w += v.w;
        }
        ((float4*)&g_c_part[0][b][chunk][0])[lane] = s;
    } else if (threadIdx.x < 64) {
        float4 s = shc[1][0][lane];
        #pragma unroll
        for (int g = 1; g < 8; g++) {
            float4 v = shc[1][g][lane];
            s.x += v.x; s.y += v.y; s.z += v.z; s.w += v.w;
        }
        ((float4*)&g_c_part[1][b][chunk][0])[lane] = s;
    }
}

// ===========================================================================
// K5: et[ti][b][t] = c[ti][b].U[:,t] + d[ti][b][t] + bias[t]
//     + per-tile softmax stats (max, sumexp) per (ti,b,tile)
// grid (NS, 4, 2), block 256: warp per batch (8 batches/block), lane -> 4 t's
// ===========================================================================
__global__ void __launch_bounds__(256) k5_et(
    const float* __restrict__ U1, const float* __restrict__ U2,
    const float* __restrict__ b1, const float* __restrict__ b2)
{
    int tb = blockIdx.x;          // tile 0..15
    int bg = blockIdx.y;          // 0..3
    int ti = blockIdx.z;          // 0..1
    const float* U = ti ? U2 : U1;
    const float* bias = ti ? b2 : b1;
    int b0 = bg * 8, t0 = tb * RPC;

    __shared__ float csh[8][E];
    for (int idx = threadIdx.x; idx < 8 * E; idx += 256) {
        int bi = idx >> 7, e = idx & 127;
        float acc = 0.f;
        #pragma unroll
        for (int ch = 0; ch < NS; ch++) acc += g_c_part[ti][b0 + bi][ch][e];
        csh[bi][e] = acc * INV_T;
    }
    __syncthreads();

    int bi = threadIdx.x >> 5, lane = threadIdx.x & 31;
    const float4* U4 = (const float4*)(U + t0) + lane;
    float4 acc = {0,0,0,0};
    #pragma unroll 8
    for (int e = 0; e < E; e++) {
        float c = csh[bi][e];
        float4 u = U4[e * (T/4)];
        acc.x = fmaf(c, u.x, acc.x);
        acc.y = fmaf(c, u.y, acc.y);
        acc.z = fmaf(c, u.z, acc.z);
        acc.w = fmaf(c, u.w, acc.w);
    }
    int t = t0 + lane * 4;
    float4 dd = *(const float4*)&g_d[ti][b0 + bi][t];
    float4 bb = *(const float4*)(bias + t);
    acc.x += dd.x + bb.x;
    acc.y += dd.y + bb.y;
    acc.z += dd.z + bb.z;
    acc.w += dd.w + bb.w;
    *(float4*)&g_et[ti][b0 + bi][t] = acc;

    // warp-level tile softmax stats (one warp covers the whole 128-t tile)
    float m = fmaxf(fmaxf(acc.x, acc.y), fmaxf(acc.z, acc.w));
    #pragma unroll
    for (int off = 16; off; off >>= 1)
        m = fmaxf(m, __shfl_xor_sync(0xffffffffu, m, off));
    float z = __expf(acc.x - m) + __expf(acc.y - m)
            + __expf(acc.z - m) + __expf(acc.w - m);
    #pragma unroll
    for (int off = 16; off; off >>= 1)
        z += __shfl_xor_sync(0xffffffffu, z, off);
    if (lane == 0)
        g_stats[ti][b0 + bi][tb] = make_float2(m, z);
}

// ===========================================================================
// K7: combine tile stats -> softmax weights (smem) -> weighted-sum partials;
//     last block per batch (ticket) reduces partials and writes the output.
// grid (NS, B), block 256
// ===========================================================================
__global__ void __launch_bounds__(256) k7_o(
    const float* __restrict__ x1, const float* __restrict__ x2,
    float* __restrict__ out)
{
    int chunk = blockIdx.x, b = blockIdx.y;
    int lane = threadIdx.x & 31, grp = threadIdx.x >> 5;
    int t0 = chunk * RPC;

    // 1) combine the 16 tile stats (2 threads only)
    __shared__ float s_m[2], s_iz[2];
    if (threadIdx.x < 2) {
        int ti = threadIdx.x;
        float m = -3.4e38f;
        #pragma unroll
        for (int i = 0; i < NS; i++) m = fmaxf(m, g_stats[ti][b][i].x);
        float z = 0.f;
        #pragma unroll
        for (int i = 0; i < NS; i++) {
            float2 st = g_stats[ti][b][i];
            z += st.y * __expf(st.x - m);
        }
        s_m[ti] = m;
        s_iz[ti] = 1.0f / z;
    }
    __syncthreads();

    // 2) materialize softmax weights for this chunk (1 exp per thread)
    __shared__ float wsh[2][RPC];
    {
        int ti = threadIdx.x >> 7, rr = threadIdx.x & 127;
        wsh[ti][rr] = __expf(g_et[ti][b][t0 + rr] - s_m[ti]) * s_iz[ti];
    }
    __syncthreads();

    // 3) weighted accumulation over the chunk
    const float4* p1 = (const float4*)(x1 + ((size_t)b * T + t0) * E) + lane;
    const float4* p2 = (const float4*)(x2 + ((size_t)b * T + t0) * E) + lane;
    float4 a1 = {0,0,0,0}, a2 = {0,0,0,0};
    #pragma unroll 4
    for (int r = grp; r < RPC; r += 8) {
        float w1 = wsh[0][r];
        float w2 = wsh[1][r];
        float4 v1 = p1[r * (E/4)];
        float4 v2 = p2[r * (E/4)];
        a1.x = fmaf(w1, v1.x, a1.x); a1.y = fmaf(w1, v1.y, a1.y);
        a1.z = fmaf(w1, v1.z, a1.z); a1.w = fmaf(w1, v1.w, a1.w);
        a2.x = fmaf(w2, v2.x, a2.x); a2.y = fmaf(w2, v2.y, a2.y);
        a2.z = fmaf(w2, v2.z, a2.z); a2.w = fmaf(w2, v2.w, a2.w);
    }

    __shared__ float4 sh1[8][32], sh2[8][32];
    sh1[grp][lane] = a1;
    sh2[grp][lane] = a2;
    __syncthreads();
    if (threadIdx.x < 32) {
        float4 s = sh1[0][lane];
        #pragma unroll
        for (int g = 1; g < 8; g++) {
            float4 v = sh1[g][lane];
            s.x += v.x; s.y += v.y; s.z += v.z; s.w += v.w;
        }
        ((float4*)&g_o_part[0][b][chunk][0])[lane] = s;
    } else if (threadIdx.x < 64) {
        float4 s = sh2[0][lane];
        #pragma unroll
        for (int g = 1; g < 8; g++) {
            float4 v = sh2[g][lane];
            s.x += v.x; s.y += v.y; s.z += v.z; s.w += v.w;
        }
        ((float4*)&g_o_part[1][b][chunk][0])[lane] = s;
    }
    __syncthreads();

    // 4) deterministic last-block final reduction (self-resetting ticket,
    //    release fence before the atomic, acquire fence after observing it)
    __shared__ int s_last;
    if (threadIdx.x == 0) {
        __threadfence();
        unsigned old = atomicInc(&g_ticket[b], NS - 1);
        s_last = (old == NS - 1);
    }
    __syncthreads();
    if (s_last) {
        __threadfence();
        int ti = threadIdx.x >> 7, e = threadIdx.x & 127;
        float acc = 0.f;
        #pragma unroll
        for (int ch = 0; ch < NS; ch++) acc += g_o_part[ti][b][ch][e];
        out[b * 256 + ti * 128 + e] = acc;
    }
}

// ===========================================================================
extern "C" void kernel_launch(void* const* d_in, const int* in_sizes, int n_in,
                              void* d_out, int out_size)
{
    const float* x1 = (const float*)d_in[0];
    const float* x2 = (const float*)d_in[1];
    const float* W1 = (const float*)d_in[2];
    const float* b1 = (const float*)d_in[3];
    const float* U1 = (const float*)d_in[4];
    const float* W2 = (const float*)d_in[5];
    const float* b2 = (const float*)d_in[6];
    const float* U2 = (const float*)d_in[7];
    float* out = (float*)d_out;

    k1_sd<<<dim3(NS, B), 256>>>(x1, x2, W1, W2);
    k3_c<<<dim3(NS, B), 256>>>(x1, x2);
    k5_et<<<dim3(NS, 4, 2), 256>>>(U1, U2, b1, b2);
    k7_o<<<dim3(NS, B), 256>>>(x1, x2, out);
}